// round 1
// baseline (speedup 1.0000x reference)
#include <cuda_runtime.h>
#include <math.h>

// Problem constants
constexpr int LN = 256;    // utterances
constexpr int DN = 300;    // embedding dim
constexpr int SN = 16;     // concepts per utterance
constexpr int KN = 16;     // dst per concept
constexpr int RN = 6;      // relation types
constexpr int EN = 2048;   // edges
constexpr int CN = 7;      // classes
constexpr float NEGV = -1000000000.0f;

// Scratch (device globals, no allocation)
__device__ float g_wrel[RN * DN * DN];       // 2.16 MB
__device__ float g_hidden[LN * DN];
__device__ float g_uttproj[RN * LN * DN];    // utt @ W_rel[r]
__device__ float g_Q[LN * DN];
__device__ float g_K[LN * DN];
__device__ float g_V[LN * DN];
__device__ float g_ctx[LN * DN];
__device__ float g_relatt[LN * DN];
__device__ float g_relnorm[LN];
__device__ float g_nodes[(long)LN * 48 * DN]; // 14.7 MB
__device__ float g_score[LN * 48];
__device__ int   g_nmask[LN * 48];
__device__ float g_feat[LN * 900];

// ---------------------------------------------------------------------------
// W_rel[r] = comp[r,0]*W_basis[0] + comp[r,1]*W_basis[1]
__global__ void wrel_kernel(const float* __restrict__ Wb, const float* __restrict__ comp) {
    int idx = blockIdx.x * blockDim.x + threadIdx.x;
    if (idx < RN * DN * DN) {
        int r = idx / (DN * DN);
        int rem = idx - r * (DN * DN);
        g_wrel[idx] = comp[r * 2] * Wb[rem] + comp[r * 2 + 1] * Wb[DN * DN + rem];
    }
}

// ---------------------------------------------------------------------------
// Generic small row-blocked matmul: out[row0+r, o] = sum_i A[row0+r, i]*W[i,o] (+bias)
// RB=8 rows per block so each block reads W once for 8 rows (W stays in L2).
__global__ void __launch_bounds__(128) rowmm_kernel(
    const float* __restrict__ A, const float* __restrict__ W,
    const float* __restrict__ bias, float* __restrict__ out,
    int Din, int Dout)
{
    constexpr int RB = 8;
    extern __shared__ float sA[];
    int row0 = blockIdx.x * RB;
    for (int idx = threadIdx.x; idx < RB * Din; idx += blockDim.x)
        sA[idx] = A[(long)row0 * Din + idx];
    __syncthreads();
    for (int o = threadIdx.x; o < Dout; o += blockDim.x) {
        float acc[RB];
#pragma unroll
        for (int r = 0; r < RB; r++) acc[r] = 0.f;
        for (int i = 0; i < Din; i++) {
            float w = W[(long)i * Dout + o];
#pragma unroll
            for (int r = 0; r < RB; r++) acc[r] += sA[r * Din + i] * w;
        }
        float b = bias ? bias[o] : 0.f;
#pragma unroll
        for (int r = 0; r < RB; r++) out[(long)(row0 + r) * Dout + o] = acc[r] + b;
    }
}

// ---------------------------------------------------------------------------
// RGCN edge scatter: hidden[dst] += uttproj[type][src]   (float atomics)
__global__ void __launch_bounds__(128) scatter_kernel(
    const int* __restrict__ src, const int* __restrict__ dst, const int* __restrict__ et)
{
    int e = blockIdx.x;
    int sl = src[e], dl = dst[e], r = et[e];
    const float* m = g_uttproj + ((long)r * LN + sl) * DN;
    float* h = g_hidden + (long)dl * DN;
    for (int d = threadIdx.x; d < DN; d += blockDim.x)
        atomicAdd(h + d, m[d]);
}

// ---------------------------------------------------------------------------
// Windowed attention context (only center q needed): ctx[l] = sum_j a[h,j]*V[win_j]
__global__ void __launch_bounds__(128) attn_ctx_kernel() {
    int l = blockIdx.x;
    int tid = threadIdx.x, warp = tid >> 5, lane = tid & 31;
    __shared__ float qsm[DN];
    __shared__ float lg[2][3];
    int w[3];
    w[0] = l > 0 ? l - 1 : 0;
    w[1] = l;
    w[2] = l < LN - 1 ? l + 1 : LN - 1;
    for (int d = tid; d < DN; d += blockDim.x) qsm[d] = g_Q[l * DN + d];
    __syncthreads();
    for (int p = warp; p < 6; p += 4) {
        int h = p / 3, j = p - 3 * h;
        const float* kr = g_K + (long)w[j] * DN + h * 150;
        const float* qh = qsm + h * 150;
        float acc = 0.f;
        for (int d = lane; d < 150; d += 32) acc += qh[d] * kr[d];
        for (int off = 16; off; off >>= 1) acc += __shfl_down_sync(0xffffffffu, acc, off);
        if (lane == 0) lg[h][j] = acc * 0.081649658092772603f;  // 1/sqrt(150)
    }
    __syncthreads();
    float a[2][3];
#pragma unroll
    for (int h = 0; h < 2; h++) {
        float m = fmaxf(lg[h][0], fmaxf(lg[h][1], lg[h][2]));
        float s = 0.f;
#pragma unroll
        for (int j = 0; j < 3; j++) { a[h][j] = expf(lg[h][j] - m); s += a[h][j]; }
        float inv = 1.f / s;
#pragma unroll
        for (int j = 0; j < 3; j++) a[h][j] *= inv;
    }
    for (int d = tid; d < DN; d += blockDim.x) {
        int h = d >= 150;
        float c = a[h][0] * g_V[(long)w[0] * DN + d]
                + a[h][1] * g_V[(long)w[1] * DN + d]
                + a[h][2] * g_V[(long)w[2] * DN + d];
        g_ctx[l * DN + d] = c;
    }
}

// ---------------------------------------------------------------------------
__global__ void norm_kernel() {
    int l = blockIdx.x;
    int lane = threadIdx.x;
    float s = 0.f;
    for (int d = lane; d < DN; d += 32) {
        float v = g_relatt[l * DN + d];
        s += v * v;
    }
    for (int off = 16; off; off >>= 1) s += __shfl_down_sync(0xffffffffu, s, off);
    if (lane == 0) g_relnorm[l] = sqrtf(s);
}

// ---------------------------------------------------------------------------
// Concept two-level attention. One block per (n,l,s).
// Caches all 16 dst rows in SMEM so each gathered row is read from global ONCE.
__global__ void __launch_bounds__(128) concept_kernel(
    const int* __restrict__ src_ids, const int* __restrict__ dst_ids,
    const float* __restrict__ wgt, const float* __restrict__ sen,
    const float* __restrict__ table, const float* __restrict__ rvecs)
{
    int s = blockIdx.x, l = blockIdx.y, n = blockIdx.z;
    int tid = threadIdx.x, warp = tid >> 5, lane = tid & 31;
    __shared__ float dstc[KN][DN];
    __shared__ float srcsm[DN], rsm[DN], relsm[DN];
    __shared__ float d_du[KN], d_nn[KN], d_dp[KN];
    __shared__ int d_val[KN];
    __shared__ float red[4];

    int sidx = (n * LN + l) * SN + s;
    int src_id = src_ids[sidx];
    const float* srow = table + (long)(src_id < 0 ? 0 : src_id) * DN;
    for (int d = tid; d < DN; d += 128) {
        srcsm[d] = srow[d];
        rsm[d] = rvecs[n * DN + d];
        relsm[d] = g_relatt[l * DN + d];
    }
    __syncthreads();

    long base = (long)sidx * KN;
    for (int k = warp; k < KN; k += 4) {
        int id = dst_ids[base + k];
        const float4* rowv = (const float4*)(table + (long)(id < 0 ? 0 : id) * DN);
        float du = 0.f, nn = 0.f, dp = 0.f;
        for (int i = lane; i < 75; i += 32) {  // 300 floats = 75 float4 (rows 16B aligned)
            float4 v = rowv[i];
            int d = i * 4;
            dstc[k][d] = v.x; dstc[k][d + 1] = v.y; dstc[k][d + 2] = v.z; dstc[k][d + 3] = v.w;
            du += relsm[d] * v.x + relsm[d + 1] * v.y + relsm[d + 2] * v.z + relsm[d + 3] * v.w;
            nn += v.x * v.x + v.y * v.y + v.z * v.z + v.w * v.w;
            dp += srcsm[d] * rsm[d] * v.x + srcsm[d + 1] * rsm[d + 1] * v.y
                + srcsm[d + 2] * rsm[d + 2] * v.z + srcsm[d + 3] * rsm[d + 3] * v.w;
        }
        for (int off = 16; off; off >>= 1) {
            du += __shfl_down_sync(0xffffffffu, du, off);
            nn += __shfl_down_sync(0xffffffffu, nn, off);
            dp += __shfl_down_sync(0xffffffffu, dp, off);
        }
        if (lane == 0) { d_du[k] = du; d_nn[k] = nn; d_dp[k] = dp; d_val[k] = (id >= 0); }
    }
    __syncthreads();

    // Per-thread redundant tiny softmaxes (16 wide) — avoids extra syncs.
    float rn = g_relnorm[l];
    float a1[KN], w2[KN];
    {
        float om[KN];
        float mx = NEGV;
#pragma unroll
        for (int k = 0; k < KN; k++) {
            if (d_val[k]) {
                float cosv = fabsf(d_du[k]) / (rn * sqrtf(d_nn[k]) + 1e-8f);
                om[k] = 0.5f * wgt[base + k] * cosv + 0.5f * fabsf(sen[base + k]);
            } else om[k] = NEGV;
            mx = fmaxf(mx, om[k]);
        }
        float sum = 0.f;
#pragma unroll
        for (int k = 0; k < KN; k++) { a1[k] = expf(om[k] - mx); sum += a1[k]; }
        float inv = 1.f / sum;
#pragma unroll
        for (int k = 0; k < KN; k++) a1[k] = a1[k] * inv * (d_val[k] ? 1.f : 0.f);

        float sk[KN], a2[KN];
        mx = NEGV;
#pragma unroll
        for (int k = 0; k < KN; k++) {
            sk[k] = d_val[k] ? a1[k] * d_dp[k] : NEGV;
            mx = fmaxf(mx, sk[k]);
        }
        sum = 0.f;
#pragma unroll
        for (int k = 0; k < KN; k++) { a2[k] = expf(sk[k] - mx); sum += a2[k]; }
        inv = 1.f / sum;
#pragma unroll
        for (int k = 0; k < KN; k++) w2[k] = a2[k] * inv * (d_val[k] ? 1.f : 0.f) * a1[k];
    }

    // src2 and its score against relatt
    float ssc = 0.f;
    long nbase = ((long)l * 48 + n * SN + s) * DN;
    for (int d = tid; d < DN; d += 128) {
        float acc = 0.f;
#pragma unroll
        for (int k = 0; k < KN; k++) acc += w2[k] * dstc[k][d];
        float v = srcsm[d] + rsm[d] * acc;
        g_nodes[nbase + d] = v;
        ssc += relsm[d] * v;
    }
    for (int off = 16; off; off >>= 1) ssc += __shfl_down_sync(0xffffffffu, ssc, off);
    if (lane == 0) red[warp] = ssc;
    __syncthreads();
    if (tid == 0) {
        g_score[l * 48 + n * SN + s] = red[0] + red[1] + red[2] + red[3];
        g_nmask[l * 48 + n * SN + s] = (src_id >= 0);
    }
}

// ---------------------------------------------------------------------------
// Node-level attention -> sym; assemble feat = [hidden | relatt | sym]
__global__ void __launch_bounds__(128) symfeat_kernel() {
    int l = blockIdx.x;
    int tid = threadIdx.x;
    __shared__ float att[48];
    __shared__ float anyf;
    if (tid == 0) {
        float v[48];
        float mx = NEGV;
        int any = 0;
        for (int j = 0; j < 48; j++) {
            int m = g_nmask[l * 48 + j];
            v[j] = m ? g_score[l * 48 + j] : NEGV;
            mx = fmaxf(mx, v[j]);
            any |= m;
        }
        float sum = 0.f;
        for (int j = 0; j < 48; j++) { v[j] = expf(v[j] - mx); sum += v[j]; }
        float inv = 1.f / sum;
        for (int j = 0; j < 48; j++) att[j] = v[j] * inv * (g_nmask[l * 48 + j] ? 1.f : 0.f);
        anyf = any ? 1.f : 0.f;
    }
    __syncthreads();
    for (int d = tid; d < DN; d += blockDim.x) {
        float acc = 0.f;
        for (int j = 0; j < 48; j++) acc += att[j] * g_nodes[((long)l * 48 + j) * DN + d];
        g_feat[l * 900 + d] = g_hidden[l * DN + d];
        g_feat[l * 900 + 300 + d] = g_relatt[l * DN + d];
        g_feat[l * 900 + 600 + d] = acc * anyf;
    }
}

// ---------------------------------------------------------------------------
// feat(900) @ W_fuse(900x300) + b -> relu -> @ W_out(300x7) + b -> log_softmax
__global__ void __launch_bounds__(128) final_kernel(
    const float* __restrict__ Wf, const float* __restrict__ bf,
    const float* __restrict__ Wo2, const float* __restrict__ bo,
    float* __restrict__ out)
{
    constexpr int RB = 8;
    __shared__ float fsm[RB * 900];
    __shared__ float hsm[RB * 300];
    __shared__ float lg[RB][8];
    int row0 = blockIdx.x * RB;
    int tid = threadIdx.x;
    for (int idx = tid; idx < RB * 900; idx += blockDim.x)
        fsm[idx] = g_feat[(long)row0 * 900 + idx];
    __syncthreads();
    for (int o = tid; o < 300; o += blockDim.x) {
        float acc[RB];
#pragma unroll
        for (int r = 0; r < RB; r++) acc[r] = 0.f;
        for (int i = 0; i < 900; i++) {
            float w = Wf[(long)i * 300 + o];
#pragma unroll
            for (int r = 0; r < RB; r++) acc[r] += fsm[r * 900 + i] * w;
        }
        float b = bf[o];
#pragma unroll
        for (int r = 0; r < RB; r++) hsm[r * 300 + o] = fmaxf(acc[r] + b, 0.f);
    }
    __syncthreads();
    for (int idx = tid; idx < RB * CN; idx += blockDim.x) {
        int r = idx / CN, c = idx - r * CN;
        float acc = 0.f;
        for (int i = 0; i < 300; i++) acc += hsm[r * 300 + i] * Wo2[i * CN + c];
        lg[r][c] = acc + bo[c];
    }
    __syncthreads();
    if (tid < RB) {
        int r = tid;
        float mx = lg[r][0];
        for (int c = 1; c < CN; c++) mx = fmaxf(mx, lg[r][c]);
        float sum = 0.f;
        for (int c = 0; c < CN; c++) sum += expf(lg[r][c] - mx);
        float ls = logf(sum) + mx;
        for (int c = 0; c < CN; c++) out[(row0 + r) * CN + c] = lg[r][c] - ls;
    }
}

// ---------------------------------------------------------------------------
extern "C" void kernel_launch(void* const* d_in, const int* in_sizes, int n_in,
                              void* d_out, int out_size)
{
    const float* utt   = (const float*)d_in[0];
    const int*   ssrc  = (const int*)d_in[1];
    const int*   sdst  = (const int*)d_in[2];
    const int*   setyp = (const int*)d_in[3];
    const int*   csrc  = (const int*)d_in[4];
    const int*   cdst  = (const int*)d_in[5];
    const float* cwgt  = (const float*)d_in[6];
    const float* csen  = (const float*)d_in[7];
    const float* table = (const float*)d_in[8];
    const float* Wb    = (const float*)d_in[9];
    const float* comp  = (const float*)d_in[10];
    const float* Wself = (const float*)d_in[11];
    const float* brg   = (const float*)d_in[12];
    const float* Wq    = (const float*)d_in[13];
    const float* Wk    = (const float*)d_in[14];
    const float* Wv    = (const float*)d_in[15];
    const float* Wo    = (const float*)d_in[16];
    const float* rvecs = (const float*)d_in[17];
    const float* Wfuse = (const float*)d_in[18];
    const float* bfuse = (const float*)d_in[19];
    const float* Wout  = (const float*)d_in[20];
    const float* bout  = (const float*)d_in[21];
    float* out = (float*)d_out;

    float *p_wrel, *p_uttproj, *p_hidden, *p_Q, *p_K, *p_V, *p_ctx, *p_relatt;
    cudaGetSymbolAddress((void**)&p_wrel, g_wrel);
    cudaGetSymbolAddress((void**)&p_uttproj, g_uttproj);
    cudaGetSymbolAddress((void**)&p_hidden, g_hidden);
    cudaGetSymbolAddress((void**)&p_Q, g_Q);
    cudaGetSymbolAddress((void**)&p_K, g_K);
    cudaGetSymbolAddress((void**)&p_V, g_V);
    cudaGetSymbolAddress((void**)&p_ctx, g_ctx);
    cudaGetSymbolAddress((void**)&p_relatt, g_relatt);

    const int SM_ROW = 8 * DN * 4;  // 9600 B

    // RGCN path
    wrel_kernel<<<(RN * DN * DN + 127) / 128, 128>>>(Wb, comp);
    rowmm_kernel<<<LN / 8, 128, SM_ROW>>>(utt, Wself, brg, p_hidden, DN, DN);
    for (int r = 0; r < RN; r++)
        rowmm_kernel<<<LN / 8, 128, SM_ROW>>>(utt, p_wrel + (long)r * DN * DN, nullptr,
                                              p_uttproj + (long)r * LN * DN, DN, DN);
    scatter_kernel<<<EN, 128>>>(ssrc, sdst, setyp);

    // Windowed attention path
    rowmm_kernel<<<LN / 8, 128, SM_ROW>>>(utt, Wq, nullptr, p_Q, DN, DN);
    rowmm_kernel<<<LN / 8, 128, SM_ROW>>>(utt, Wk, nullptr, p_K, DN, DN);
    rowmm_kernel<<<LN / 8, 128, SM_ROW>>>(utt, Wv, nullptr, p_V, DN, DN);
    attn_ctx_kernel<<<LN, 128>>>();
    rowmm_kernel<<<LN / 8, 128, SM_ROW>>>(p_ctx, Wo, nullptr, p_relatt, DN, DN);
    norm_kernel<<<LN, 32>>>();

    // Concept graph attention (dominant gather)
    concept_kernel<<<dim3(SN, LN, 3), 128>>>(csrc, cdst, cwgt, csen, table, rvecs);

    // Node attention + fusion head
    symfeat_kernel<<<LN, 128>>>();
    final_kernel<<<LN / 8, 128>>>(Wfuse, bfuse, Wout, bout, out);
}

// round 3
// speedup vs baseline: 3.8815x; 3.8815x over previous
#include <cuda_runtime.h>
#include <math.h>

// Problem constants
constexpr int LN = 256;    // utterances
constexpr int DN = 300;    // embedding dim
constexpr int SN = 16;     // concepts per utterance
constexpr int KN = 16;     // dst per concept
constexpr int EN = 2048;   // edges
constexpr int CN = 7;      // classes
constexpr float NEGV = -1000000000.0f;

// Scratch (device globals, no allocation)
__device__ float g_hidden[LN * DN];
__device__ float g_P0[LN * DN];   // utt @ W_basis[0]
__device__ float g_P1[LN * DN];   // utt @ W_basis[1]
__device__ float g_Q[LN * DN];
__device__ float g_K[LN * DN];
__device__ float g_V[LN * DN];
__device__ float g_ctx[LN * DN];
__device__ float g_relatt[LN * DN];
__device__ float g_relnorm[LN];
__device__ float g_nodes[(long)LN * 48 * DN]; // 14.7 MB
__device__ float g_score[LN * 48];
__device__ int   g_nmask[LN * 48];
__device__ float g_feat[LN * 900];

// ---------------------------------------------------------------------------
// Tiled SGEMM tile body: O[32x64 tile] = A[256x300] @ W[300x300] (+bias)
// blockIdx.x = N tile (5), blockIdx.y = M tile (8). 256 threads, 2x4 micro-tile.
__device__ __forceinline__ void gemm_tile(
    const float* __restrict__ A, const float* __restrict__ W,
    const float* __restrict__ bias, float* __restrict__ O)
{
    __shared__ float As[32][33];
    __shared__ __align__(16) float Ws[32][64];
    int t = threadIdx.x;
    int m0 = blockIdx.y * 32, n0 = blockIdx.x * 64;
    int row0 = (t >> 4) * 2;
    int col0 = (t & 15) * 4;
    float acc[2][4] = {};
    for (int k0 = 0; k0 < DN; k0 += 32) {
#pragma unroll
        for (int i = 0; i < 4; i++) {
            int idx = t + i * 256;
            int r = idx >> 5, c = idx & 31;
            As[r][c] = (k0 + c < DN) ? A[(m0 + r) * DN + k0 + c] : 0.f;
        }
#pragma unroll
        for (int i = 0; i < 8; i++) {
            int idx = t + i * 256;
            int r = idx >> 6, c = idx & 63;
            int kk = k0 + r, nn = n0 + c;
            Ws[r][c] = (kk < DN && nn < DN) ? W[kk * DN + nn] : 0.f;
        }
        __syncthreads();
#pragma unroll
        for (int k = 0; k < 32; k++) {
            float4 w4 = *(const float4*)&Ws[k][col0];
            float a0 = As[row0][k], a1 = As[row0 + 1][k];
            acc[0][0] += a0 * w4.x; acc[0][1] += a0 * w4.y;
            acc[0][2] += a0 * w4.z; acc[0][3] += a0 * w4.w;
            acc[1][0] += a1 * w4.x; acc[1][1] += a1 * w4.y;
            acc[1][2] += a1 * w4.z; acc[1][3] += a1 * w4.w;
        }
        __syncthreads();
    }
#pragma unroll
    for (int i = 0; i < 2; i++) {
        int m = m0 + row0 + i;
#pragma unroll
        for (int j = 0; j < 4; j++) {
            int n = n0 + col0 + j;
            if (n < DN)
                O[m * DN + n] = acc[i][j] + (bias ? bias[n] : 0.f);
        }
    }
}

// Batched: z selects which of 6 projections of utt we compute.
__global__ void __launch_bounds__(256) gemm6_kernel(
    const float* __restrict__ utt,
    const float* __restrict__ Wself, const float* __restrict__ brg,
    const float* __restrict__ Wb,
    const float* __restrict__ Wq, const float* __restrict__ Wk2,
    const float* __restrict__ Wv)
{
    int z = blockIdx.z;
    const float* Wz;
    float* Oz;
    const float* bz = nullptr;
    switch (z) {
        case 0: Wz = Wself; Oz = g_hidden; bz = brg; break;
        case 1: Wz = Wb;            Oz = g_P0; break;
        case 2: Wz = Wb + DN * DN;  Oz = g_P1; break;
        case 3: Wz = Wq;  Oz = g_Q; break;
        case 4: Wz = Wk2; Oz = g_K; break;
        default: Wz = Wv; Oz = g_V; break;
    }
    gemm_tile(utt, Wz, bz, Oz);
}

// Single GEMM: relatt = ctx @ Wo
__global__ void __launch_bounds__(256) gemmWo_kernel(const float* __restrict__ Wo)
{
    gemm_tile(g_ctx, Wo, nullptr, g_relatt);
}

// ---------------------------------------------------------------------------
// RGCN edge scatter: hidden[dst] += comp[et,0]*P0[src] + comp[et,1]*P1[src]
__global__ void __launch_bounds__(128) scatter_kernel(
    const int* __restrict__ src, const int* __restrict__ dst,
    const int* __restrict__ et, const float* __restrict__ comp)
{
    int e = blockIdx.x;
    int sl = src[e], dl = dst[e], r = et[e];
    float c0 = comp[2 * r], c1 = comp[2 * r + 1];
    const float* p0 = g_P0 + (long)sl * DN;
    const float* p1 = g_P1 + (long)sl * DN;
    float* h = g_hidden + (long)dl * DN;
    for (int d = threadIdx.x; d < DN; d += blockDim.x)
        atomicAdd(h + d, c0 * p0[d] + c1 * p1[d]);
}

// ---------------------------------------------------------------------------
// Windowed attention context (only center q needed): ctx[l] = sum_j a[h,j]*V[win_j]
__global__ void __launch_bounds__(128) attn_ctx_kernel() {
    int l = blockIdx.x;
    int tid = threadIdx.x, warp = tid >> 5, lane = tid & 31;
    __shared__ float qsm[DN];
    __shared__ float lg[2][3];
    int w[3];
    w[0] = l > 0 ? l - 1 : 0;
    w[1] = l;
    w[2] = l < LN - 1 ? l + 1 : LN - 1;
    for (int d = tid; d < DN; d += blockDim.x) qsm[d] = g_Q[l * DN + d];
    __syncthreads();
    for (int p = warp; p < 6; p += 4) {
        int h = p / 3, j = p - 3 * h;
        const float* kr = g_K + (long)w[j] * DN + h * 150;
        const float* qh = qsm + h * 150;
        float acc = 0.f;
        for (int d = lane; d < 150; d += 32) acc += qh[d] * kr[d];
        for (int off = 16; off; off >>= 1) acc += __shfl_down_sync(0xffffffffu, acc, off);
        if (lane == 0) lg[h][j] = acc * 0.081649658092772603f;  // 1/sqrt(150)
    }
    __syncthreads();
    float a[2][3];
#pragma unroll
    for (int h = 0; h < 2; h++) {
        float m = fmaxf(lg[h][0], fmaxf(lg[h][1], lg[h][2]));
        float s = 0.f;
#pragma unroll
        for (int j = 0; j < 3; j++) { a[h][j] = expf(lg[h][j] - m); s += a[h][j]; }
        float inv = 1.f / s;
#pragma unroll
        for (int j = 0; j < 3; j++) a[h][j] *= inv;
    }
    for (int d = tid; d < DN; d += blockDim.x) {
        int h = d >= 150;
        float c = a[h][0] * g_V[(long)w[0] * DN + d]
                + a[h][1] * g_V[(long)w[1] * DN + d]
                + a[h][2] * g_V[(long)w[2] * DN + d];
        g_ctx[l * DN + d] = c;
    }
}

// ---------------------------------------------------------------------------
__global__ void norm_kernel() {
    int l = blockIdx.x;
    int lane = threadIdx.x;
    float s = 0.f;
    for (int d = lane; d < DN; d += 32) {
        float v = g_relatt[l * DN + d];
        s += v * v;
    }
    for (int off = 16; off; off >>= 1) s += __shfl_down_sync(0xffffffffu, s, off);
    if (lane == 0) g_relnorm[l] = sqrtf(s);
}

// ---------------------------------------------------------------------------
// Concept two-level attention. One block per (n,l,s).
// Caches all 16 dst rows in SMEM so each gathered row is read from global ONCE.
__global__ void __launch_bounds__(128) concept_kernel(
    const int* __restrict__ src_ids, const int* __restrict__ dst_ids,
    const float* __restrict__ wgt, const float* __restrict__ sen,
    const float* __restrict__ table, const float* __restrict__ rvecs)
{
    int s = blockIdx.x, l = blockIdx.y, n = blockIdx.z;
    int tid = threadIdx.x, warp = tid >> 5, lane = tid & 31;
    __shared__ float dstc[KN][DN];
    __shared__ float srcsm[DN], rsm[DN], relsm[DN];
    __shared__ float d_du[KN], d_nn[KN], d_dp[KN];
    __shared__ int d_val[KN];
    __shared__ float red[4];

    int sidx = (n * LN + l) * SN + s;
    int src_id = src_ids[sidx];
    const float* srow = table + (long)(src_id < 0 ? 0 : src_id) * DN;
    for (int d = tid; d < DN; d += 128) {
        srcsm[d] = srow[d];
        rsm[d] = rvecs[n * DN + d];
        relsm[d] = g_relatt[l * DN + d];
    }
    __syncthreads();

    long base = (long)sidx * KN;
    for (int k = warp; k < KN; k += 4) {
        int id = dst_ids[base + k];
        const float4* rowv = (const float4*)(table + (long)(id < 0 ? 0 : id) * DN);
        float du = 0.f, nn = 0.f, dp = 0.f;
        for (int i = lane; i < 75; i += 32) {  // 300 floats = 75 float4 (rows 16B aligned)
            float4 v = rowv[i];
            int d = i * 4;
            dstc[k][d] = v.x; dstc[k][d + 1] = v.y; dstc[k][d + 2] = v.z; dstc[k][d + 3] = v.w;
            du += relsm[d] * v.x + relsm[d + 1] * v.y + relsm[d + 2] * v.z + relsm[d + 3] * v.w;
            nn += v.x * v.x + v.y * v.y + v.z * v.z + v.w * v.w;
            dp += srcsm[d] * rsm[d] * v.x + srcsm[d + 1] * rsm[d + 1] * v.y
                + srcsm[d + 2] * rsm[d + 2] * v.z + srcsm[d + 3] * rsm[d + 3] * v.w;
        }
        for (int off = 16; off; off >>= 1) {
            du += __shfl_down_sync(0xffffffffu, du, off);
            nn += __shfl_down_sync(0xffffffffu, nn, off);
            dp += __shfl_down_sync(0xffffffffu, dp, off);
        }
        if (lane == 0) { d_du[k] = du; d_nn[k] = nn; d_dp[k] = dp; d_val[k] = (id >= 0); }
    }
    __syncthreads();

    // Per-thread redundant tiny softmaxes (16 wide) — avoids extra syncs.
    float rn = g_relnorm[l];
    float a1[KN], w2[KN];
    {
        float om[KN];
        float mx = NEGV;
#pragma unroll
        for (int k = 0; k < KN; k++) {
            if (d_val[k]) {
                float cosv = fabsf(d_du[k]) / (rn * sqrtf(d_nn[k]) + 1e-8f);
                om[k] = 0.5f * wgt[base + k] * cosv + 0.5f * fabsf(sen[base + k]);
            } else om[k] = NEGV;
            mx = fmaxf(mx, om[k]);
        }
        float sum = 0.f;
#pragma unroll
        for (int k = 0; k < KN; k++) { a1[k] = expf(om[k] - mx); sum += a1[k]; }
        float inv = 1.f / sum;
#pragma unroll
        for (int k = 0; k < KN; k++) a1[k] = a1[k] * inv * (d_val[k] ? 1.f : 0.f);

        float sk[KN], a2[KN];
        mx = NEGV;
#pragma unroll
        for (int k = 0; k < KN; k++) {
            sk[k] = d_val[k] ? a1[k] * d_dp[k] : NEGV;
            mx = fmaxf(mx, sk[k]);
        }
        sum = 0.f;
#pragma unroll
        for (int k = 0; k < KN; k++) { a2[k] = expf(sk[k] - mx); sum += a2[k]; }
        inv = 1.f / sum;
#pragma unroll
        for (int k = 0; k < KN; k++) w2[k] = a2[k] * inv * (d_val[k] ? 1.f : 0.f) * a1[k];
    }

    // src2 and its score against relatt
    float ssc = 0.f;
    long nbase = ((long)l * 48 + n * SN + s) * DN;
    for (int d = tid; d < DN; d += 128) {
        float acc = 0.f;
#pragma unroll
        for (int k = 0; k < KN; k++) acc += w2[k] * dstc[k][d];
        float v = srcsm[d] + rsm[d] * acc;
        g_nodes[nbase + d] = v;
        ssc += relsm[d] * v;
    }
    for (int off = 16; off; off >>= 1) ssc += __shfl_down_sync(0xffffffffu, ssc, off);
    if (lane == 0) red[warp] = ssc;
    __syncthreads();
    if (tid == 0) {
        g_score[l * 48 + n * SN + s] = red[0] + red[1] + red[2] + red[3];
        g_nmask[l * 48 + n * SN + s] = (src_id >= 0);
    }
}

// ---------------------------------------------------------------------------
// Node-level attention -> sym; assemble feat = [hidden | relatt | sym]
__global__ void __launch_bounds__(128) symfeat_kernel() {
    int l = blockIdx.x;
    int tid = threadIdx.x;
    __shared__ float att[48];
    __shared__ float anyf;
    if (tid == 0) {
        float v[48];
        float mx = NEGV;
        int any = 0;
        for (int j = 0; j < 48; j++) {
            int m = g_nmask[l * 48 + j];
            v[j] = m ? g_score[l * 48 + j] : NEGV;
            mx = fmaxf(mx, v[j]);
            any |= m;
        }
        float sum = 0.f;
        for (int j = 0; j < 48; j++) { v[j] = expf(v[j] - mx); sum += v[j]; }
        float inv = 1.f / sum;
        for (int j = 0; j < 48; j++) att[j] = v[j] * inv * (g_nmask[l * 48 + j] ? 1.f : 0.f);
        anyf = any ? 1.f : 0.f;
    }
    __syncthreads();
    for (int d = tid; d < DN; d += blockDim.x) {
        float acc = 0.f;
        for (int j = 0; j < 48; j++) acc += att[j] * g_nodes[((long)l * 48 + j) * DN + d];
        g_feat[l * 900 + d] = g_hidden[l * DN + d];
        g_feat[l * 900 + 300 + d] = g_relatt[l * DN + d];
        g_feat[l * 900 + 600 + d] = acc * anyf;
    }
}

// ---------------------------------------------------------------------------
// feat(900) @ W_fuse(900x300) + b -> relu -> @ W_out(300x7) + b -> log_softmax
__global__ void __launch_bounds__(128) final_kernel(
    const float* __restrict__ Wf, const float* __restrict__ bf,
    const float* __restrict__ Wo2, const float* __restrict__ bo,
    float* __restrict__ out)
{
    constexpr int RB = 8;
    __shared__ float fsm[RB * 900];
    __shared__ float hsm[RB * 300];
    __shared__ float lg[RB][8];
    int row0 = blockIdx.x * RB;
    int tid = threadIdx.x;
    for (int idx = tid; idx < RB * 900; idx += blockDim.x)
        fsm[idx] = g_feat[(long)row0 * 900 + idx];
    __syncthreads();
    for (int o = tid; o < 300; o += blockDim.x) {
        float acc[RB];
#pragma unroll
        for (int r = 0; r < RB; r++) acc[r] = 0.f;
        for (int i = 0; i < 900; i++) {
            float w = Wf[(long)i * 300 + o];
#pragma unroll
            for (int r = 0; r < RB; r++) acc[r] += fsm[r * 900 + i] * w;
        }
        float b = bf[o];
#pragma unroll
        for (int r = 0; r < RB; r++) hsm[r * 300 + o] = fmaxf(acc[r] + b, 0.f);
    }
    __syncthreads();
    for (int idx = tid; idx < RB * CN; idx += blockDim.x) {
        int r = idx / CN, c = idx - r * CN;
        float acc = 0.f;
        for (int i = 0; i < 300; i++) acc += hsm[r * 300 + i] * Wo2[i * CN + c];
        lg[r][c] = acc + bo[c];
    }
    __syncthreads();
    if (tid < RB) {
        int r = tid;
        float mx = lg[r][0];
        for (int c = 1; c < CN; c++) mx = fmaxf(mx, lg[r][c]);
        float sum = 0.f;
        for (int c = 0; c < CN; c++) sum += expf(lg[r][c] - mx);
        float ls = logf(sum) + mx;
        for (int c = 0; c < CN; c++) out[(row0 + r) * CN + c] = lg[r][c] - ls;
    }
}

// ---------------------------------------------------------------------------
extern "C" void kernel_launch(void* const* d_in, const int* in_sizes, int n_in,
                              void* d_out, int out_size)
{
    const float* utt   = (const float*)d_in[0];
    const int*   ssrc  = (const int*)d_in[1];
    const int*   sdst  = (const int*)d_in[2];
    const int*   setyp = (const int*)d_in[3];
    const int*   csrc  = (const int*)d_in[4];
    const int*   cdst  = (const int*)d_in[5];
    const float* cwgt  = (const float*)d_in[6];
    const float* csen  = (const float*)d_in[7];
    const float* table = (const float*)d_in[8];
    const float* Wb    = (const float*)d_in[9];
    const float* comp  = (const float*)d_in[10];
    const float* Wself = (const float*)d_in[11];
    const float* brg   = (const float*)d_in[12];
    const float* Wq    = (const float*)d_in[13];
    const float* Wk    = (const float*)d_in[14];
    const float* Wv    = (const float*)d_in[15];
    const float* Wo    = (const float*)d_in[16];
    const float* rvecs = (const float*)d_in[17];
    const float* Wfuse = (const float*)d_in[18];
    const float* bfuse = (const float*)d_in[19];
    const float* Wout  = (const float*)d_in[20];
    const float* bout  = (const float*)d_in[21];
    float* out = (float*)d_out;

    dim3 ggrid(5, 8, 6);   // 5 N-tiles x 8 M-tiles x 6 matrices

    // Fused projections: hidden(self)+bias, P0, P1, Q, K, V
    gemm6_kernel<<<ggrid, 256>>>(utt, Wself, brg, Wb, Wq, Wk, Wv);

    // RGCN edge scatter (uses hidden, P0, P1)
    scatter_kernel<<<EN, 128>>>(ssrc, sdst, setyp, comp);

    // Windowed attention path
    attn_ctx_kernel<<<LN, 128>>>();
    gemmWo_kernel<<<dim3(5, 8, 1), 256>>>(Wo);
    norm_kernel<<<LN, 32>>>();

    // Concept graph attention (dominant gather)
    concept_kernel<<<dim3(SN, LN, 3), 128>>>(csrc, cdst, cwgt, csen, table, rvecs);

    // Node attention + fusion head
    symfeat_kernel<<<LN, 128>>>();
    final_kernel<<<LN / 8, 128>>>(Wfuse, bfuse, Wout, bout, out);
}

// round 4
// speedup vs baseline: 6.3751x; 1.6424x over previous
#include <cuda_runtime.h>
#include <math.h>

// Problem constants
constexpr int LN = 256;    // utterances
constexpr int DN = 300;    // embedding dim
constexpr int SN = 16;     // concepts per utterance
constexpr int KN = 16;     // dst per concept
constexpr int EN = 2048;   // edges
constexpr int CN = 7;      // classes
constexpr float NEGV = -1000000000.0f;

// Scratch (device globals, no allocation)
__device__ float g_hidden[LN * DN];
__device__ float g_P0[LN * DN];   // utt @ W_basis[0]
__device__ float g_P1[LN * DN];   // utt @ W_basis[1]
__device__ float g_Q[LN * DN];
__device__ float g_K[LN * DN];
__device__ float g_V[LN * DN];
__device__ float g_ctx[LN * DN];
__device__ float g_relatt[LN * DN];
__device__ float g_nodes[(long)LN * 48 * DN]; // 14.7 MB
__device__ float g_score[LN * 48];
__device__ int   g_nmask[LN * 48];
__device__ float g_feat[LN * 900];
__device__ float g_fuse[LN * DN];

// ---------------------------------------------------------------------------
// Double-buffered tiled SGEMM: O[32x64 tile] = A[256 x Kdim] @ W[Kdim x 300]
// blockIdx.x = N tile, blockIdx.y = M tile. 256 threads, 2x4 micro-tile.
// Next K-chunk is prefetched into registers while computing the current one,
// so L2 latency is not exposed behind __syncthreads.
__device__ __forceinline__ void gemm_core(
    const float* __restrict__ A, const float* __restrict__ W,
    const float* __restrict__ bias, float* __restrict__ O,
    int Kdim, bool relu)
{
    __shared__ float As[2][32][33];
    __shared__ __align__(16) float Ws[2][32][64];
    int t = threadIdx.x;
    int m0 = blockIdx.y * 32, n0 = blockIdx.x * 64;
    int row0 = (t >> 4) * 2;
    int col0 = (t & 15) * 4;
    int ar = t >> 5, ac = t & 31;   // A loader: rows ar+8i, col ac
    int wr = t >> 6, wc = t & 63;   // W loader: rows wr+4i, col wc
    float acc[2][4] = {};
    int nchunks = (Kdim + 31) >> 5;

    float a_reg[4], w_reg[8];
#pragma unroll
    for (int i = 0; i < 4; i++)
        a_reg[i] = (ac < Kdim) ? A[(m0 + ar + i * 8) * Kdim + ac] : 0.f;
#pragma unroll
    for (int i = 0; i < 8; i++) {
        int kk = wr + i * 4, nn = n0 + wc;
        w_reg[i] = (kk < Kdim && nn < DN) ? W[kk * DN + nn] : 0.f;
    }
#pragma unroll
    for (int i = 0; i < 4; i++) As[0][ar + i * 8][ac] = a_reg[i];
#pragma unroll
    for (int i = 0; i < 8; i++) Ws[0][wr + i * 4][wc] = w_reg[i];
    __syncthreads();

    for (int c = 1; c < nchunks; c++) {
        int k0 = c << 5;
        // prefetch chunk c into registers (overlaps with compute below)
#pragma unroll
        for (int i = 0; i < 4; i++) {
            int kk = k0 + ac;
            a_reg[i] = (kk < Kdim) ? A[(m0 + ar + i * 8) * Kdim + kk] : 0.f;
        }
#pragma unroll
        for (int i = 0; i < 8; i++) {
            int kk = k0 + wr + i * 4, nn = n0 + wc;
            w_reg[i] = (kk < Kdim && nn < DN) ? W[kk * DN + nn] : 0.f;
        }
        int cur = (c - 1) & 1;
#pragma unroll
        for (int k = 0; k < 32; k++) {
            float4 w4 = *(const float4*)&Ws[cur][k][col0];
            float a0 = As[cur][row0][k], a1 = As[cur][row0 + 1][k];
            acc[0][0] += a0 * w4.x; acc[0][1] += a0 * w4.y;
            acc[0][2] += a0 * w4.z; acc[0][3] += a0 * w4.w;
            acc[1][0] += a1 * w4.x; acc[1][1] += a1 * w4.y;
            acc[1][2] += a1 * w4.z; acc[1][3] += a1 * w4.w;
        }
        __syncthreads();
        int nxt = c & 1;
#pragma unroll
        for (int i = 0; i < 4; i++) As[nxt][ar + i * 8][ac] = a_reg[i];
#pragma unroll
        for (int i = 0; i < 8; i++) Ws[nxt][wr + i * 4][wc] = w_reg[i];
        __syncthreads();
    }
    int cur = (nchunks - 1) & 1;
#pragma unroll
    for (int k = 0; k < 32; k++) {
        float4 w4 = *(const float4*)&Ws[cur][k][col0];
        float a0 = As[cur][row0][k], a1 = As[cur][row0 + 1][k];
        acc[0][0] += a0 * w4.x; acc[0][1] += a0 * w4.y;
        acc[0][2] += a0 * w4.z; acc[0][3] += a0 * w4.w;
        acc[1][0] += a1 * w4.x; acc[1][1] += a1 * w4.y;
        acc[1][2] += a1 * w4.z; acc[1][3] += a1 * w4.w;
    }

#pragma unroll
    for (int i = 0; i < 2; i++) {
        int m = m0 + row0 + i;
#pragma unroll
        for (int j = 0; j < 4; j++) {
            int n = n0 + col0 + j;
            if (n < DN) {
                float v = acc[i][j] + (bias ? bias[n] : 0.f);
                O[m * DN + n] = relu ? fmaxf(v, 0.f) : v;
            }
        }
    }
}

// Batched: z selects which of 6 projections of utt we compute.
__global__ void __launch_bounds__(256) gemm6_kernel(
    const float* __restrict__ utt,
    const float* __restrict__ Wself, const float* __restrict__ brg,
    const float* __restrict__ Wb,
    const float* __restrict__ Wq, const float* __restrict__ Wk2,
    const float* __restrict__ Wv)
{
    int z = blockIdx.z;
    const float* Wz;
    float* Oz;
    const float* bz = nullptr;
    switch (z) {
        case 0: Wz = Wself; Oz = g_hidden; bz = brg; break;
        case 1: Wz = Wb;            Oz = g_P0; break;
        case 2: Wz = Wb + DN * DN;  Oz = g_P1; break;
        case 3: Wz = Wq;  Oz = g_Q; break;
        case 4: Wz = Wk2; Oz = g_K; break;
        default: Wz = Wv; Oz = g_V; break;
    }
    gemm_core(utt, Wz, bz, Oz, DN, false);
}

// relatt = ctx @ Wo
__global__ void __launch_bounds__(256) gemmWo_kernel(const float* __restrict__ Wo)
{
    gemm_core(g_ctx, Wo, nullptr, g_relatt, DN, false);
}

// fuse = relu(feat @ Wfuse + bfuse)   (K = 900)
__global__ void __launch_bounds__(256) gemmFuse_kernel(
    const float* __restrict__ Wf, const float* __restrict__ bf)
{
    gemm_core(g_feat, Wf, bf, g_fuse, 900, true);
}

// ---------------------------------------------------------------------------
// RGCN edge scatter: hidden[dst] += comp[et,0]*P0[src] + comp[et,1]*P1[src]
__global__ void __launch_bounds__(128) scatter_kernel(
    const int* __restrict__ src, const int* __restrict__ dst,
    const int* __restrict__ et, const float* __restrict__ comp)
{
    int e = blockIdx.x;
    int sl = src[e], dl = dst[e], r = et[e];
    float c0 = comp[2 * r], c1 = comp[2 * r + 1];
    const float* p0 = g_P0 + (long)sl * DN;
    const float* p1 = g_P1 + (long)sl * DN;
    float* h = g_hidden + (long)dl * DN;
    for (int d = threadIdx.x; d < DN; d += blockDim.x)
        atomicAdd(h + d, c0 * p0[d] + c1 * p1[d]);
}

// ---------------------------------------------------------------------------
// Windowed attention context (only center q needed): ctx[l] = sum_j a[h,j]*V[win_j]
__global__ void __launch_bounds__(128) attn_ctx_kernel() {
    int l = blockIdx.x;
    int tid = threadIdx.x, warp = tid >> 5, lane = tid & 31;
    __shared__ float qsm[DN];
    __shared__ float lg[2][3];
    int w[3];
    w[0] = l > 0 ? l - 1 : 0;
    w[1] = l;
    w[2] = l < LN - 1 ? l + 1 : LN - 1;
    for (int d = tid; d < DN; d += blockDim.x) qsm[d] = g_Q[l * DN + d];
    __syncthreads();
    for (int p = warp; p < 6; p += 4) {
        int h = p / 3, j = p - 3 * h;
        const float* kr = g_K + (long)w[j] * DN + h * 150;
        const float* qh = qsm + h * 150;
        float acc = 0.f;
        for (int d = lane; d < 150; d += 32) acc += qh[d] * kr[d];
        for (int off = 16; off; off >>= 1) acc += __shfl_down_sync(0xffffffffu, acc, off);
        if (lane == 0) lg[h][j] = acc * 0.081649658092772603f;  // 1/sqrt(150)
    }
    __syncthreads();
    float a[2][3];
#pragma unroll
    for (int h = 0; h < 2; h++) {
        float m = fmaxf(lg[h][0], fmaxf(lg[h][1], lg[h][2]));
        float s = 0.f;
#pragma unroll
        for (int j = 0; j < 3; j++) { a[h][j] = expf(lg[h][j] - m); s += a[h][j]; }
        float inv = 1.f / s;
#pragma unroll
        for (int j = 0; j < 3; j++) a[h][j] *= inv;
    }
    for (int d = tid; d < DN; d += blockDim.x) {
        int h = d >= 150;
        float c = a[h][0] * g_V[(long)w[0] * DN + d]
                + a[h][1] * g_V[(long)w[1] * DN + d]
                + a[h][2] * g_V[(long)w[2] * DN + d];
        g_ctx[l * DN + d] = c;
    }
}

// ---------------------------------------------------------------------------
// Concept two-level attention. One block per (n,l,s), 256 threads (8 warps).
// Caches all 16 dst rows in SMEM so each gathered row is read from global ONCE.
// relatt norm computed in-block (norm_kernel folded in).
__global__ void __launch_bounds__(256) concept_kernel(
    const int* __restrict__ src_ids, const int* __restrict__ dst_ids,
    const float* __restrict__ wgt, const float* __restrict__ sen,
    const float* __restrict__ table, const float* __restrict__ rvecs)
{
    int s = blockIdx.x, l = blockIdx.y, n = blockIdx.z;
    int tid = threadIdx.x, warp = tid >> 5, lane = tid & 31;
    __shared__ __align__(16) float dstc[KN][DN];
    __shared__ __align__(16) float srcsm[DN], rsm[DN], relsm[DN];
    __shared__ float d_du[KN], d_nn[KN], d_dp[KN];
    __shared__ int d_val[KN];
    __shared__ float red[8];
    __shared__ float s_nrm;

    int sidx = (n * LN + l) * SN + s;
    int src_id = src_ids[sidx];
    const float4* srow4 = (const float4*)(table + (long)(src_id < 0 ? 0 : src_id) * DN);
    const float4* rel4 = (const float4*)(g_relatt + (long)l * DN);
    const float4* rv4 = (const float4*)(rvecs + (long)n * DN);
    if (tid == 0) s_nrm = 0.f;
    __syncthreads();
    if (tid < 75) {
        float4 v = rel4[tid];
        *(float4*)&relsm[tid * 4] = v;
        atomicAdd(&s_nrm, v.x * v.x + v.y * v.y + v.z * v.z + v.w * v.w);
    } else if (tid < 150) {
        *(float4*)&rsm[(tid - 75) * 4] = rv4[tid - 75];
    } else if (tid < 225) {
        *(float4*)&srcsm[(tid - 150) * 4] = srow4[tid - 150];
    }
    __syncthreads();

    long base = (long)sidx * KN;
    for (int k = warp; k < KN; k += 8) {
        int id = dst_ids[base + k];
        const float4* rowv = (const float4*)(table + (long)(id < 0 ? 0 : id) * DN);
        float du = 0.f, nn = 0.f, dp = 0.f;
        for (int i = lane; i < 75; i += 32) {  // 300 floats = 75 float4 (rows 16B aligned)
            float4 v = rowv[i];
            int d = i * 4;
            *(float4*)&dstc[k][d] = v;
            du += relsm[d] * v.x + relsm[d + 1] * v.y + relsm[d + 2] * v.z + relsm[d + 3] * v.w;
            nn += v.x * v.x + v.y * v.y + v.z * v.z + v.w * v.w;
            dp += srcsm[d] * rsm[d] * v.x + srcsm[d + 1] * rsm[d + 1] * v.y
                + srcsm[d + 2] * rsm[d + 2] * v.z + srcsm[d + 3] * rsm[d + 3] * v.w;
        }
        for (int off = 16; off; off >>= 1) {
            du += __shfl_down_sync(0xffffffffu, du, off);
            nn += __shfl_down_sync(0xffffffffu, nn, off);
            dp += __shfl_down_sync(0xffffffffu, dp, off);
        }
        if (lane == 0) { d_du[k] = du; d_nn[k] = nn; d_dp[k] = dp; d_val[k] = (id >= 0); }
    }
    __syncthreads();

    // Tiny softmaxes, redundantly per active thread (only tid<75 need them).
    float ssc = 0.f;
    if (tid < 75) {
        float rn = sqrtf(s_nrm);
        float a1[KN], w2[KN];
        {
            float om[KN];
            float mx = NEGV;
#pragma unroll
            for (int k = 0; k < KN; k++) {
                if (d_val[k]) {
                    float cosv = fabsf(d_du[k]) / (rn * sqrtf(d_nn[k]) + 1e-8f);
                    om[k] = 0.5f * wgt[base + k] * cosv + 0.5f * fabsf(sen[base + k]);
                } else om[k] = NEGV;
                mx = fmaxf(mx, om[k]);
            }
            float sum = 0.f;
#pragma unroll
            for (int k = 0; k < KN; k++) { a1[k] = expf(om[k] - mx); sum += a1[k]; }
            float inv = 1.f / sum;
#pragma unroll
            for (int k = 0; k < KN; k++) a1[k] = a1[k] * inv * (d_val[k] ? 1.f : 0.f);

            float sk[KN], a2[KN];
            mx = NEGV;
#pragma unroll
            for (int k = 0; k < KN; k++) {
                sk[k] = d_val[k] ? a1[k] * d_dp[k] : NEGV;
                mx = fmaxf(mx, sk[k]);
            }
            sum = 0.f;
#pragma unroll
            for (int k = 0; k < KN; k++) { a2[k] = expf(sk[k] - mx); sum += a2[k]; }
            inv = 1.f / sum;
#pragma unroll
            for (int k = 0; k < KN; k++) w2[k] = a2[k] * inv * (d_val[k] ? 1.f : 0.f) * a1[k];
        }

        // src2 (float4) and its score against relatt
        int d = tid * 4;
        float4 a = make_float4(0.f, 0.f, 0.f, 0.f);
#pragma unroll
        for (int k = 0; k < KN; k++) {
            float4 dv = *(const float4*)&dstc[k][d];
            a.x += w2[k] * dv.x; a.y += w2[k] * dv.y;
            a.z += w2[k] * dv.z; a.w += w2[k] * dv.w;
        }
        float4 sv = *(const float4*)&srcsm[d];
        float4 rv = *(const float4*)&rsm[d];
        float4 v;
        v.x = sv.x + rv.x * a.x; v.y = sv.y + rv.y * a.y;
        v.z = sv.z + rv.z * a.z; v.w = sv.w + rv.w * a.w;
        long nbase = ((long)l * 48 + n * SN + s) * DN;
        *(float4*)(g_nodes + nbase + d) = v;
        ssc = relsm[d] * v.x + relsm[d + 1] * v.y + relsm[d + 2] * v.z + relsm[d + 3] * v.w;
    }
    for (int off = 16; off; off >>= 1) ssc += __shfl_down_sync(0xffffffffu, ssc, off);
    if (lane == 0) red[warp] = ssc;
    __syncthreads();
    if (tid == 0) {
        g_score[l * 48 + n * SN + s] = red[0] + red[1] + red[2];
        g_nmask[l * 48 + n * SN + s] = (src_id >= 0);
    }
}

// ---------------------------------------------------------------------------
// Node-level attention -> sym; assemble feat = [hidden | relatt | sym] (float4)
__global__ void __launch_bounds__(128) symfeat_kernel() {
    int l = blockIdx.x;
    int tid = threadIdx.x;
    __shared__ float att[48];
    __shared__ float anyf;
    if (tid == 0) {
        float v[48];
        float mx = NEGV;
        int any = 0;
        for (int j = 0; j < 48; j++) {
            int m = g_nmask[l * 48 + j];
            v[j] = m ? g_score[l * 48 + j] : NEGV;
            mx = fmaxf(mx, v[j]);
            any |= m;
        }
        float sum = 0.f;
        for (int j = 0; j < 48; j++) { v[j] = expf(v[j] - mx); sum += v[j]; }
        float inv = 1.f / sum;
        for (int j = 0; j < 48; j++) att[j] = v[j] * inv * (g_nmask[l * 48 + j] ? 1.f : 0.f);
        anyf = any ? 1.f : 0.f;
    }
    __syncthreads();
    if (tid < 75) {
        const float4* nodes4 = (const float4*)g_nodes;
        float4 acc = make_float4(0.f, 0.f, 0.f, 0.f);
#pragma unroll 8
        for (int j = 0; j < 48; j++) {
            float4 v = nodes4[((long)l * 48 + j) * 75 + tid];
            float a = att[j];
            acc.x += a * v.x; acc.y += a * v.y; acc.z += a * v.z; acc.w += a * v.w;
        }
        float an = anyf;
        acc.x *= an; acc.y *= an; acc.z *= an; acc.w *= an;
        float4* feat4 = (float4*)g_feat;
        const float4* hid4 = (const float4*)g_hidden;
        const float4* rel4 = (const float4*)g_relatt;
        feat4[(long)l * 225 + tid] = hid4[(long)l * 75 + tid];
        feat4[(long)l * 225 + 75 + tid] = rel4[(long)l * 75 + tid];
        feat4[(long)l * 225 + 150 + tid] = acc;
    }
}

// ---------------------------------------------------------------------------
// head: out[l] = log_softmax(fuse[l] @ W_out + b_out). One warp per row.
__global__ void __launch_bounds__(256) head_kernel(
    const float* __restrict__ Wo2, const float* __restrict__ bo,
    float* __restrict__ out)
{
    int l = blockIdx.x * 8 + (threadIdx.x >> 5);
    int lane = threadIdx.x & 31;
    float acc[CN];
#pragma unroll
    for (int c = 0; c < CN; c++) acc[c] = 0.f;
    const float* hrow = g_fuse + (long)l * DN;
    for (int i = lane; i < DN; i += 32) {
        float h = hrow[i];
#pragma unroll
        for (int c = 0; c < CN; c++) acc[c] += h * Wo2[i * CN + c];
    }
#pragma unroll
    for (int c = 0; c < CN; c++)
        for (int off = 16; off; off >>= 1)
            acc[c] += __shfl_down_sync(0xffffffffu, acc[c], off);
    if (lane == 0) {
        float lg[CN];
        float mx = NEGV;
#pragma unroll
        for (int c = 0; c < CN; c++) { lg[c] = acc[c] + bo[c]; mx = fmaxf(mx, lg[c]); }
        float sum = 0.f;
#pragma unroll
        for (int c = 0; c < CN; c++) sum += expf(lg[c] - mx);
        float ls = logf(sum) + mx;
#pragma unroll
        for (int c = 0; c < CN; c++) out[l * CN + c] = lg[c] - ls;
    }
}

// ---------------------------------------------------------------------------
extern "C" void kernel_launch(void* const* d_in, const int* in_sizes, int n_in,
                              void* d_out, int out_size)
{
    const float* utt   = (const float*)d_in[0];
    const int*   ssrc  = (const int*)d_in[1];
    const int*   sdst  = (const int*)d_in[2];
    const int*   setyp = (const int*)d_in[3];
    const int*   csrc  = (const int*)d_in[4];
    const int*   cdst  = (const int*)d_in[5];
    const float* cwgt  = (const float*)d_in[6];
    const float* csen  = (const float*)d_in[7];
    const float* table = (const float*)d_in[8];
    const float* Wb    = (const float*)d_in[9];
    const float* comp  = (const float*)d_in[10];
    const float* Wself = (const float*)d_in[11];
    const float* brg   = (const float*)d_in[12];
    const float* Wq    = (const float*)d_in[13];
    const float* Wk    = (const float*)d_in[14];
    const float* Wv    = (const float*)d_in[15];
    const float* Wo    = (const float*)d_in[16];
    const float* rvecs = (const float*)d_in[17];
    const float* Wfuse = (const float*)d_in[18];
    const float* bfuse = (const float*)d_in[19];
    const float* Wout  = (const float*)d_in[20];
    const float* bout  = (const float*)d_in[21];
    float* out = (float*)d_out;

    // Fused projections: hidden(self)+bias, P0, P1, Q, K, V
    gemm6_kernel<<<dim3(5, 8, 6), 256>>>(utt, Wself, brg, Wb, Wq, Wk, Wv);

    // RGCN edge scatter (uses hidden, P0, P1)
    scatter_kernel<<<EN, 128>>>(ssrc, sdst, setyp, comp);

    // Windowed attention path
    attn_ctx_kernel<<<LN, 128>>>();
    gemmWo_kernel<<<dim3(5, 8, 1), 256>>>(Wo);

    // Concept graph attention (dominant gather; norm folded in)
    concept_kernel<<<dim3(SN, LN, 3), 256>>>(csrc, cdst, cwgt, csen, table, rvecs);

    // Node attention + fusion head
    symfeat_kernel<<<LN, 128>>>();
    gemmFuse_kernel<<<dim3(5, 8, 1), 256>>>(Wfuse, bfuse);
    head_kernel<<<LN / 8, 256>>>(Wout, bout, out);
}